// round 2
// baseline (speedup 1.0000x reference)
#include <cuda_runtime.h>
#include <math.h>

// Problem constants (fixed by the dataset)
#define TSTEPS  32
#define NBATCH  20000
#define HDIM    128
#define CDIM    10

// Tiling: 16 batch rows per CTA, 256 threads.
//  - thread j = tid & 127 owns output column j
//  - half = tid >> 7 : half 0 handles local rows 0..7, half 1 rows 8..15
#define ROWS    16
#define RT      8          // rows per thread
#define HSTRIDE 144        // h_sh row stride in floats; 144 % 32 == 16 -> conflict-free stats reads

typedef unsigned long long u64;

union F4U  { float4 f4; u64 u[2]; float f[4]; };
union U64F2 { u64 u; float2 f2; };

// Packed fp32x2 FMA (Blackwell). d.lo = a.lo*b.lo + c.lo ; d.hi likewise.
__device__ __forceinline__ u64 ffma2(u64 a, u64 b, u64 c) {
    u64 d;
    asm("fma.rn.f32x2 %0, %1, %2, %3;" : "=l"(d) : "l"(a), "l"(b), "l"(c));
    return d;
}

// ---- shared memory layout (float offsets) ----
#define OFF_WIH  0                         // [32][128] float4 : W_ih k-transposed, 4-k packs
#define OFF_WHH  16384                     // [32][128] float4 : W_hh same
#define OFF_X    32768                     // [16][128] x tile
#define OFF_H    34816                     // [16][144] h tile (padded stride)
#define OFF_WD   (OFF_H + ROWS*HSTRIDE)    // [10][128] dense W
#define OFF_BSUM (OFF_WD + 1280)           // [128] b_ih + b_hh
#define OFF_G    (OFF_BSUM + 128)          // [128] gamma
#define OFF_BE   (OFF_G + 128)             // [128] beta
#define OFF_C1   (OFF_BE + 128)            // [128] gamma * attn_w
#define OFF_AW   (OFF_C1 + 128)            // [128] attn_w
#define OFF_MU   (OFF_AW + 128)            // [16]
#define OFF_RS   (OFF_MU + 16)             // [16]
#define OFF_SC   (OFF_RS + 16)             // [16]
#define OFF_E    (OFF_SC + 16)             // [16]
#define OFF_ZI   (OFF_E + 16)              // [16]
#define OFF_CC   (OFF_ZI + 16)             // [2]  C2 = sum(gamma*aw), C3 = sum(beta*aw)+attn_b
#define SMEM_FLOATS (OFF_CC + 2)
#define SMEM_BYTES  (SMEM_FLOATS * 4)      // ~156.5 KB -> one CTA per SM

extern "C" __global__ void __launch_bounds__(256, 1)
fused_rnn_attn(const float* __restrict__ X,
               const float* __restrict__ Wih, const float* __restrict__ Whh,
               const float* __restrict__ bih, const float* __restrict__ bhh,
               const float* __restrict__ gamma, const float* __restrict__ beta,
               const float* __restrict__ attnW, const float* __restrict__ attnB,
               const float* __restrict__ denseW, const float* __restrict__ denseB,
               float* __restrict__ out)
{
    extern __shared__ float sm[];
    float4* wih4 = (float4*)(sm + OFF_WIH);
    float4* whh4 = (float4*)(sm + OFF_WHH);
    float*  x_sh = sm + OFF_X;
    float*  h_sh = sm + OFF_H;

    const int tid  = threadIdx.x;
    const int j    = tid & 127;
    const int half = tid >> 7;
    const int rb   = half * RT;            // local row base for the GEMM mapping
    const int b0   = blockIdx.x * ROWS;    // global batch-row base

    // ---- stage weights / params into SMEM ----
    // wih4[q*128 + j] = float4(W_ih[j][4q .. 4q+3])  (k-transposed, 4-k packed)
    #pragma unroll 4
    for (int idx = tid; idx < 4096; idx += 256) {
        int jj = idx & 127, q = idx >> 7;
        wih4[q*128 + jj] = *(const float4*)(Wih + jj*128 + q*4);
        whh4[q*128 + jj] = *(const float4*)(Whh + jj*128 + q*4);
    }
    if (tid < 128) {
        float gv = gamma[tid], bv = beta[tid], av = attnW[tid];
        sm[OFF_BSUM + tid] = bih[tid] + bhh[tid];
        sm[OFF_G  + tid] = gv;
        sm[OFF_BE + tid] = bv;
        sm[OFF_C1 + tid] = gv * av;
        sm[OFF_AW + tid] = av;
    }
    #pragma unroll 2
    for (int idx = tid; idx < 1280; idx += 256)
        sm[OFF_WD + idx] = denseW[idx];

    {   // X[0] tile (16 rows x 128 cols, contiguous in GMEM)
        const float4* xg = (const float4*)(X + (size_t)b0 * HDIM);
        ((float4*)x_sh)[tid]       = xg[tid];
        ((float4*)x_sh)[tid + 256] = xg[tid + 256];
    }
    __syncthreads();

    if (tid == 0) {
        float C2 = 0.f, C3 = 0.f;
        for (int k = 0; k < 128; k++) {
            C2 += sm[OFF_C1 + k];
            C3 += sm[OFF_BE + k] * sm[OFF_AW + k];
        }
        sm[OFF_CC + 0] = C2;
        sm[OFF_CC + 1] = C3 + attnB[0];
    }

    const float bs = sm[OFF_BSUM + j];
    const float gj = sm[OFF_G + j];
    const float bj = sm[OFF_BE + j];

    // ---- h0 = X[0] @ W_ih^T + (b_ih + b_hh), NO relu (reference init branch) ----
    {
        u64 acc[RT];
        #pragma unroll
        for (int r = 0; r < RT; r++) acc[r] = 0ull;
        #pragma unroll 8
        for (int q = 0; q < 32; q++) {
            F4U wi; wi.f4 = wih4[q*128 + j];
            #pragma unroll
            for (int r = 0; r < RT; r++) {
                F4U xv; xv.f4 = ((const float4*)x_sh)[(rb + r)*32 + q];
                acc[r] = ffma2(xv.u[0], wi.u[0], acc[r]);
                acc[r] = ffma2(xv.u[1], wi.u[1], acc[r]);
            }
        }
        #pragma unroll
        for (int r = 0; r < RT; r++) {
            U64F2 a; a.u = acc[r];
            h_sh[(rb + r)*HSTRIDE + j] = a.f2.x + a.f2.y + bs;  // first write, no sync needed before
        }
    }
    __syncthreads();

    const float C2 = sm[OFF_CC + 0];
    const float C3 = sm[OFF_CC + 1];

    // Online-softmax state in y-space: Yacc[j] = sum_t a_t * y_t[j]  (per row)
    float Yacc[RT];
    #pragma unroll
    for (int r = 0; r < RT; r++) Yacc[r] = 0.f;
    float m_run = -INFINITY, Z_run = 0.f;   // per stats-row, replicated across the 16 group lanes

    const int srow = tid >> 4;              // stats row 0..15 (16 lanes per row)
    const int sq   = tid & 15;

    #pragma unroll 1
    for (int t = 0; t < TSTEPS; t++) {
        // prefetch next x tile into registers (hidden under the GEMM)
        float4 xp0, xp1;
        if (t < TSTEPS - 1) {
            const float4* xg = (const float4*)(X + ((size_t)(t+1)*NBATCH + b0) * HDIM);
            xp0 = xg[tid];
            xp1 = xg[tid + 256];
        }

        // ---- fused GEMM: acc = x @ W_ih^T + h @ W_hh^T  (f32x2 packed even/odd-k) ----
        u64 acc[RT];
        #pragma unroll
        for (int r = 0; r < RT; r++) acc[r] = 0ull;
        #pragma unroll 8
        for (int q = 0; q < 32; q++) {
            F4U wi; wi.f4 = wih4[q*128 + j];
            F4U wh; wh.f4 = whh4[q*128 + j];
            #pragma unroll
            for (int r = 0; r < RT; r++) {
                F4U xv; xv.f4 = ((const float4*)x_sh)[(rb + r)*32 + q];              // broadcast
                F4U hv; hv.f4 = *(const float4*)(h_sh + (rb + r)*HSTRIDE + q*4);     // broadcast
                acc[r] = ffma2(xv.u[0], wi.u[0], acc[r]);
                acc[r] = ffma2(xv.u[1], wi.u[1], acc[r]);
                acc[r] = ffma2(hv.u[0], wh.u[0], acc[r]);
                acc[r] = ffma2(hv.u[1], wh.u[1], acc[r]);
            }
        }
        float hn[RT];
        #pragma unroll
        for (int r = 0; r < RT; r++) {
            U64F2 a; a.u = acc[r];
            hn[r] = fmaxf(a.f2.x + a.f2.y + bs, 0.f);
        }

        __syncthreads();                    // all reads of x_sh / h_sh complete
        #pragma unroll
        for (int r = 0; r < RT; r++)
            h_sh[(rb + r)*HSTRIDE + j] = hn[r];
        if (t < TSTEPS - 1) {
            ((float4*)x_sh)[tid]       = xp0;
            ((float4*)x_sh)[tid + 256] = xp1;
        }
        __syncthreads();                    // new h / new x visible

        // ---- fused LN stats + attention logit: one 3-value reduction per row ----
        {
            const float* hr = h_sh + srow*HSTRIDE;
            float s1 = 0.f, s2 = 0.f, s3 = 0.f;
            #pragma unroll
            for (int i = 0; i < 8; i++) {
                float v = hr[sq + 16*i];            // conflict-free (HSTRIDE % 32 == 16)
                float c = sm[OFF_C1 + sq + 16*i];   // broadcast pairs
                s1 += v;
                s2 = fmaf(v, v, s2);
                s3 = fmaf(v, c, s3);
            }
            #pragma unroll
            for (int off = 1; off < 16; off <<= 1) {
                s1 += __shfl_xor_sync(0xffffffffu, s1, off);
                s2 += __shfl_xor_sync(0xffffffffu, s2, off);
                s3 += __shfl_xor_sync(0xffffffffu, s3, off);
            }
            float mu  = s1 * 0.0078125f;                       // /128
            float var = fmaf(s2, 0.0078125f, -mu*mu);
            float rs  = rsqrtf(var + 1e-5f);
            // s = sum_j y_j * aw_j + ab  folded through LN:  rs*(S3 - mu*C2) + C3
            float s   = fmaf(rs, s3 - mu*C2, C3);
            float mn    = fmaxf(m_run, s);
            float scale = __expf(m_run - mn);                  // 0 on first step (m_run = -inf)
            float e     = __expf(s - mn);
            Z_run = fmaf(Z_run, scale, e);
            m_run = mn;
            if (sq == 0) {
                sm[OFF_MU + srow] = mu;
                sm[OFF_RS + srow] = rs;
                sm[OFF_SC + srow] = scale;
                sm[OFF_E  + srow] = e;
            }
        }
        __syncthreads();

        // ---- online attention accumulation in y-space ----
        #pragma unroll
        for (int r = 0; r < RT; r++) {
            int row = rb + r;
            float y = fmaf((hn[r] - sm[OFF_MU + row]) * sm[OFF_RS + row], gj, bj);
            Yacc[r] = fmaf(Yacc[r], sm[OFF_SC + row], sm[OFF_E + row] * y);
        }
    }

    // ---- finalize: out[n][c] = (sum_j Wd[c][j] * Yacc[j]) / Z + b_d[c] ----
    #pragma unroll
    for (int r = 0; r < RT; r++)
        h_sh[(rb + r)*HSTRIDE + j] = Yacc[r];   // h_sh is dead; reuse as staging
    if (sq == 0)
        sm[OFF_ZI + srow] = 1.0f / Z_run;
    __syncthreads();

    {
        const float* yr = h_sh + srow*HSTRIDE;
        float p[CDIM];
        #pragma unroll
        for (int c = 0; c < CDIM; c++) p[c] = 0.f;
        #pragma unroll
        for (int i = 0; i < 8; i++) {
            float v = yr[sq + 16*i];
            #pragma unroll
            for (int c = 0; c < CDIM; c++)
                p[c] = fmaf(v, sm[OFF_WD + c*128 + sq + 16*i], p[c]);
        }
        #pragma unroll
        for (int off = 1; off < 16; off <<= 1) {
            #pragma unroll
            for (int c = 0; c < CDIM; c++)
                p[c] += __shfl_xor_sync(0xffffffffu, p[c], off);
        }
        if (sq == 0) {
            float zi = sm[OFF_ZI + srow];
            int n = b0 + srow;
            #pragma unroll
            for (int c = 0; c < CDIM; c++)
                out[n*CDIM + c] = fmaf(p[c], zi, denseB[c]);
        }
    }
}

extern "C" void kernel_launch(void* const* d_in, const int* in_sizes, int n_in,
                              void* d_out, int out_size) {
    (void)in_sizes; (void)n_in; (void)out_size;
    cudaFuncSetAttribute(fused_rnn_attn,
                         cudaFuncAttributeMaxDynamicSharedMemorySize, SMEM_BYTES);
    fused_rnn_attn<<<NBATCH / ROWS, 256, SMEM_BYTES>>>(
        (const float*)d_in[0],  // X
        (const float*)d_in[1],  // W_ih
        (const float*)d_in[2],  // W_hh
        (const float*)d_in[3],  // b_ih
        (const float*)d_in[4],  // b_hh
        (const float*)d_in[5],  // ln_gamma
        (const float*)d_in[6],  // ln_beta
        (const float*)d_in[7],  // attn_W
        (const float*)d_in[8],  // attn_b
        (const float*)d_in[9],  // dense_W
        (const float*)d_in[10], // dense_b
        (float*)d_out);
}

// round 3
// speedup vs baseline: 1.4283x; 1.4283x over previous
#include <cuda_runtime.h>
#include <math.h>
#include <stdint.h>

// Problem constants (fixed by the dataset)
#define TSTEPS  32
#define NBATCH  20000
#define HDIM    128
#define CDIM    10

// Tiling: 32 batch rows per CTA, 256 threads.
//  - j0 = tid & 63 : thread owns output columns {j0, j0+64}   (CJ = 2)
//  - grp = tid >> 6 (0..3) : rows grp*8 .. grp*8+7             (RT = 8)
#define ROWS    32
#define RT      8
#define CJ      2
#define HSTRIDE 136        // h row stride in floats; 136 % 32 == 8 -> conflict-free stats reads
#define HBUF    (ROWS*HSTRIDE)   // 4352 floats per h buffer
#define XBUF    (ROWS*HDIM)      // 4096 floats per x buffer

typedef unsigned long long u64;

union F4U   { float4 f4; u64 u[2]; float f[4]; };
union U64F2 { u64 u; float2 f2; };

// Packed fp32x2 FMA (Blackwell): d.lo = a.lo*b.lo + c.lo ; d.hi likewise.
__device__ __forceinline__ u64 ffma2(u64 a, u64 b, u64 c) {
    u64 d;
    asm("fma.rn.f32x2 %0, %1, %2, %3;" : "=l"(d) : "l"(a), "l"(b), "l"(c));
    return d;
}

__device__ __forceinline__ void cp_async16(uint32_t saddr, const void* gptr) {
    asm volatile("cp.async.cg.shared.global [%0], [%1], 16;" :: "r"(saddr), "l"(gptr));
}
#define CP_COMMIT() asm volatile("cp.async.commit_group;" ::: "memory")
#define CP_WAIT0()  asm volatile("cp.async.wait_group 0;"  ::: "memory")

// ---- shared memory layout (float offsets) ----
#define OFF_WIH  0                          // [32 q][128 j] float4 : W_ih k-transposed, 4-k packs
#define OFF_WHH  16384                      // [32 q][128 j] float4 : W_hh same
#define OFF_X    32768                      // [2][32][128] x tiles (double buffer)
#define OFF_H    (OFF_X + 2*XBUF)           // [2][32][136] h tiles (double buffer)
#define OFF_WD   (OFF_H + 2*HBUF)           // [10][128] dense W
#define OFF_BSUM (OFF_WD + 1280)            // [128] b_ih + b_hh
#define OFF_G    (OFF_BSUM + 128)           // [128] gamma
#define OFF_BE   (OFF_G + 128)              // [128] beta
#define OFF_C1   (OFF_BE + 128)             // [128] gamma * attn_w
#define OFF_MU   (OFF_C1 + 128)             // [32]
#define OFF_RS   (OFF_MU + 32)              // [32]
#define OFF_SC   (OFF_RS + 32)              // [32]
#define OFF_E    (OFF_SC + 32)              // [32]
#define OFF_ZI   (OFF_E + 32)               // [32]
#define OFF_CC   (OFF_ZI + 32)              // [2]
#define SMEM_FLOATS (OFF_CC + 2)
#define SMEM_BYTES  (SMEM_FLOATS * 4)       // ~206.5 KB -> one CTA per SM

extern "C" __global__ void __launch_bounds__(256, 1)
fused_rnn_attn(const float* __restrict__ X,
               const float* __restrict__ Wih, const float* __restrict__ Whh,
               const float* __restrict__ bih, const float* __restrict__ bhh,
               const float* __restrict__ gamma, const float* __restrict__ beta,
               const float* __restrict__ attnW, const float* __restrict__ attnB,
               const float* __restrict__ denseW, const float* __restrict__ denseB,
               float* __restrict__ out)
{
    extern __shared__ float sm[];
    float4* wih4 = (float4*)(sm + OFF_WIH);
    float4* whh4 = (float4*)(sm + OFF_WHH);

    const int tid = threadIdx.x;
    const int j0  = tid & 63;
    const int grp = tid >> 6;            // 0..3
    const int rb  = grp * RT;            // local row base
    const int b0  = blockIdx.x * ROWS;   // global batch-row base

    // ---- stage X[0] tile via cp.async (perfectly coalesced) ----
    {
        uint32_t sx = (uint32_t)__cvta_generic_to_shared(sm + OFF_X);  // buffer 0
        const float4* xg = (const float4*)(X + (size_t)b0 * HDIM);
        #pragma unroll
        for (int c = 0; c < 4; c++)
            cp_async16(sx + (tid + 256*c) * 16, xg + tid + 256*c);
        CP_COMMIT();
    }

    // ---- stage weights / params into SMEM ----
    #pragma unroll 4
    for (int idx = tid; idx < 4096; idx += 256) {
        int jj = idx & 127, q = idx >> 7;
        wih4[q*128 + jj] = *(const float4*)(Wih + jj*128 + q*4);
        whh4[q*128 + jj] = *(const float4*)(Whh + jj*128 + q*4);
    }
    if (tid < 128) {
        float gv = gamma[tid], bv = beta[tid], av = attnW[tid];
        sm[OFF_BSUM + tid] = bih[tid] + bhh[tid];
        sm[OFF_G  + tid] = gv;
        sm[OFF_BE + tid] = bv;
        sm[OFF_C1 + tid] = gv * av;
    }
    #pragma unroll 2
    for (int idx = tid; idx < 1280; idx += 256)
        sm[OFF_WD + idx] = denseW[idx];

    CP_WAIT0();
    __syncthreads();

    if (tid == 0) {
        float C2 = 0.f, C3 = 0.f;
        for (int k = 0; k < 128; k++) {
            C2 += sm[OFF_C1 + k];
            C3 += beta[k] * attnW[k];
        }
        sm[OFF_CC + 0] = C2;
        sm[OFF_CC + 1] = C3 + attnB[0];
    }

    const float bs0 = sm[OFF_BSUM + j0];
    const float bs1 = sm[OFF_BSUM + j0 + 64];
    const float gj0 = sm[OFF_G + j0],  gj1 = sm[OFF_G + j0 + 64];
    const float bj0 = sm[OFF_BE + j0], bj1 = sm[OFF_BE + j0 + 64];

    // ---- h0 = X[0] @ W_ih^T + (b_ih + b_hh), NO relu (reference init branch) ----
    {
        const float4* x4 = (const float4*)(sm + OFF_X);   // buffer 0
        float* hw = sm + OFF_H;                           // h buffer 0
        u64 acc[RT][CJ];
        #pragma unroll
        for (int r = 0; r < RT; r++) { acc[r][0] = 0ull; acc[r][1] = 0ull; }
        #pragma unroll 4
        for (int q = 0; q < 32; q++) {
            F4U wi0; wi0.f4 = wih4[q*128 + j0];
            F4U wi1; wi1.f4 = wih4[q*128 + j0 + 64];
            #pragma unroll
            for (int r = 0; r < RT; r++) {
                F4U xv; xv.f4 = x4[(rb + r)*32 + q];      // broadcast
                acc[r][0] = ffma2(xv.u[0], wi0.u[0], acc[r][0]);
                acc[r][0] = ffma2(xv.u[1], wi0.u[1], acc[r][0]);
                acc[r][1] = ffma2(xv.u[0], wi1.u[0], acc[r][1]);
                acc[r][1] = ffma2(xv.u[1], wi1.u[1], acc[r][1]);
            }
        }
        #pragma unroll
        for (int r = 0; r < RT; r++) {
            U64F2 a0; a0.u = acc[r][0];
            U64F2 a1; a1.u = acc[r][1];
            hw[(rb + r)*HSTRIDE + j0]      = a0.f2.x + a0.f2.y + bs0;
            hw[(rb + r)*HSTRIDE + j0 + 64] = a1.f2.x + a1.f2.y + bs1;
        }
    }
    __syncthreads();

    const float C2 = sm[OFF_CC + 0];
    const float C3 = sm[OFF_CC + 1];

    // Online-softmax state in y-space
    float Yacc[RT][CJ];
    #pragma unroll
    for (int r = 0; r < RT; r++) { Yacc[r][0] = 0.f; Yacc[r][1] = 0.f; }
    float m_run = -INFINITY, Z_run = 0.f;

    const int srow = tid >> 3;            // stats row 0..31 (8 lanes per row)
    const int sq   = tid & 7;

    #pragma unroll 1
    for (int t = 0; t < TSTEPS; t++) {
        const int pb = t & 1, nb = pb ^ 1;

        // prefetch next x tile into SMEM buffer nb (off the register file / issue path)
        if (t < TSTEPS - 1) {
            uint32_t sx = (uint32_t)__cvta_generic_to_shared(sm + OFF_X + nb*XBUF);
            const float4* xg = (const float4*)(X + ((size_t)(t+1)*NBATCH + b0) * HDIM);
            #pragma unroll
            for (int c = 0; c < 4; c++)
                cp_async16(sx + (tid + 256*c) * 16, xg + tid + 256*c);
            CP_COMMIT();
        }

        // ---- fused GEMM: acc = x @ W_ih^T + h @ W_hh^T  (2 cols x 8 rows per thread) ----
        const float4* x4 = (const float4*)(sm + OFF_X + pb*XBUF);
        const float4* h4 = (const float4*)(sm + OFF_H + pb*HBUF);
        u64 acc[RT][CJ];
        #pragma unroll
        for (int r = 0; r < RT; r++) { acc[r][0] = 0ull; acc[r][1] = 0ull; }
        #pragma unroll 4
        for (int q = 0; q < 32; q++) {
            F4U wi0; wi0.f4 = wih4[q*128 + j0];
            F4U wi1; wi1.f4 = wih4[q*128 + j0 + 64];
            F4U wh0; wh0.f4 = whh4[q*128 + j0];
            F4U wh1; wh1.f4 = whh4[q*128 + j0 + 64];
            #pragma unroll
            for (int r = 0; r < RT; r++) {
                F4U xv; xv.f4 = x4[(rb + r)*32 + q];              // broadcast
                F4U hv; hv.f4 = h4[(rb + r)*34 + q];              // broadcast (136/4 = 34)
                acc[r][0] = ffma2(xv.u[0], wi0.u[0], acc[r][0]);
                acc[r][0] = ffma2(xv.u[1], wi0.u[1], acc[r][0]);
                acc[r][0] = ffma2(hv.u[0], wh0.u[0], acc[r][0]);
                acc[r][0] = ffma2(hv.u[1], wh0.u[1], acc[r][0]);
                acc[r][1] = ffma2(xv.u[0], wi1.u[0], acc[r][1]);
                acc[r][1] = ffma2(xv.u[1], wi1.u[1], acc[r][1]);
                acc[r][1] = ffma2(hv.u[0], wh1.u[0], acc[r][1]);
                acc[r][1] = ffma2(hv.u[1], wh1.u[1], acc[r][1]);
            }
        }
        float hn[RT][CJ];
        #pragma unroll
        for (int r = 0; r < RT; r++) {
            U64F2 a0; a0.u = acc[r][0];
            U64F2 a1; a1.u = acc[r][1];
            hn[r][0] = fmaxf(a0.f2.x + a0.f2.y + bs0, 0.f);
            hn[r][1] = fmaxf(a1.f2.x + a1.f2.y + bs1, 0.f);
        }

        // write new h into buffer nb (no WAR with buffer pb -> no barrier needed first)
        float* hw = sm + OFF_H + nb*HBUF;
        #pragma unroll
        for (int r = 0; r < RT; r++) {
            hw[(rb + r)*HSTRIDE + j0]      = hn[r][0];
            hw[(rb + r)*HSTRIDE + j0 + 64] = hn[r][1];
        }
        if (t < TSTEPS - 1) CP_WAIT0();
        __syncthreads();   // h[nb] + x[nb] visible; all reads of pb buffers are done

        // ---- fused LN stats + attention logit: 3-value reduction over 8 lanes ----
        {
            const float* hr = sm + OFF_H + nb*HBUF + srow*HSTRIDE;
            float s1 = 0.f, s2 = 0.f, s3 = 0.f;
            #pragma unroll
            for (int i = 0; i < 16; i++) {
                float v = hr[sq + 8*i];             // conflict-free (HSTRIDE % 32 == 8)
                float c = sm[OFF_C1 + sq + 8*i];    // broadcast
                s1 += v;
                s2 = fmaf(v, v, s2);
                s3 = fmaf(v, c, s3);
            }
            #pragma unroll
            for (int off = 1; off < 8; off <<= 1) {
                s1 += __shfl_xor_sync(0xffffffffu, s1, off);
                s2 += __shfl_xor_sync(0xffffffffu, s2, off);
                s3 += __shfl_xor_sync(0xffffffffu, s3, off);
            }
            float mu  = s1 * 0.0078125f;                    // /128
            float var = fmaf(s2, 0.0078125f, -mu*mu);
            float rs  = rsqrtf(var + 1e-5f);
            float s   = fmaf(rs, s3 - mu*C2, C3);           // attention logit
            float mn    = fmaxf(m_run, s);
            float scale = __expf(m_run - mn);               // 0 at t=0 (m_run = -inf)
            float e     = __expf(s - mn);
            Z_run = fmaf(Z_run, scale, e);
            m_run = mn;
            if (sq == 0) {
                sm[OFF_MU + srow] = mu;
                sm[OFF_RS + srow] = rs;
                sm[OFF_SC + srow] = scale;
                sm[OFF_E  + srow] = e;
            }
        }
        __syncthreads();

        // ---- online attention accumulation in y-space (hn still in registers) ----
        #pragma unroll
        for (int r = 0; r < RT; r++) {
            int row = rb + r;
            float mu = sm[OFF_MU + row], rs = sm[OFF_RS + row];
            float sc = sm[OFF_SC + row], e  = sm[OFF_E  + row];
            float y0 = fmaf((hn[r][0] - mu) * rs, gj0, bj0);
            float y1 = fmaf((hn[r][1] - mu) * rs, gj1, bj1);
            Yacc[r][0] = fmaf(Yacc[r][0], sc, e * y0);
            Yacc[r][1] = fmaf(Yacc[r][1], sc, e * y1);
        }
    }

    // ---- finalize: out[n][c] = (sum_j Wd[c][j] * Yacc[j]) / Z + b_d[c] ----
    __syncthreads();   // all t-loop reads of h buffers done before reuse as staging
    {
        float* hw = sm + OFF_H;   // reuse buffer 0 as Yacc staging
        #pragma unroll
        for (int r = 0; r < RT; r++) {
            hw[(rb + r)*HSTRIDE + j0]      = Yacc[r][0];
            hw[(rb + r)*HSTRIDE + j0 + 64] = Yacc[r][1];
        }
        if (sq == 0)
            sm[OFF_ZI + srow] = 1.0f / Z_run;
    }
    __syncthreads();

    {
        const float* yr = sm + OFF_H + srow*HSTRIDE;
        float p[CDIM];
        #pragma unroll
        for (int c = 0; c < CDIM; c++) p[c] = 0.f;
        #pragma unroll
        for (int i = 0; i < 16; i++) {
            float v = yr[sq + 8*i];
            #pragma unroll
            for (int c = 0; c < CDIM; c++)
                p[c] = fmaf(v, sm[OFF_WD + c*128 + sq + 8*i], p[c]);
        }
        #pragma unroll
        for (int off = 1; off < 8; off <<= 1) {
            #pragma unroll
            for (int c = 0; c < CDIM; c++)
                p[c] += __shfl_xor_sync(0xffffffffu, p[c], off);
        }
        if (sq == 0) {
            float zi = sm[OFF_ZI + srow];
            int n = b0 + srow;
            #pragma unroll
            for (int c = 0; c < CDIM; c++)
                out[n*CDIM + c] = fmaf(p[c], zi, denseB[c]);
        }
    }
}

extern "C" void kernel_launch(void* const* d_in, const int* in_sizes, int n_in,
                              void* d_out, int out_size) {
    (void)in_sizes; (void)n_in; (void)out_size;
    cudaFuncSetAttribute(fused_rnn_attn,
                         cudaFuncAttributeMaxDynamicSharedMemorySize, SMEM_BYTES);
    fused_rnn_attn<<<NBATCH / ROWS, 256, SMEM_BYTES>>>(
        (const float*)d_in[0],  // X
        (const float*)d_in[1],  // W_ih
        (const float*)d_in[2],  // W_hh
        (const float*)d_in[3],  // b_ih
        (const float*)d_in[4],  // b_hh
        (const float*)d_in[5],  // ln_gamma
        (const float*)d_in[6],  // ln_beta
        (const float*)d_in[7],  // attn_W
        (const float*)d_in[8],  // attn_b
        (const float*)d_in[9],  // dense_W
        (const float*)d_in[10], // dense_b
        (float*)d_out);
}